// round 4
// baseline (speedup 1.0000x reference)
#include <cuda_runtime.h>
#include <cuda_fp16.h>

#define NMAX 100000
#define EMAX 3200000
#define HD 32

// ---------------- scratch (static __device__, no allocation) ----------------
__device__ __align__(16) __half d_Th[NMAX * HD];  // fp16 per-node transform [V,h]@W_top
__device__ __align__(16) float  d_u[NMAX * HD];   // h @ W_n_top (pre-relu node update)
__device__ float2 d_V[NMAX];                      // running V
__device__ __align__(16) uint2  d_csr[EMAX];      // (sender, mask bits), CSR order
__device__ __align__(16) int    d_rowptr[NMAX + 8];
__device__ __align__(16) int    d_cursor[NMAX + 8];
__device__ __align__(16) float4 d_S4[NMAX];       // sum(mask*ef) per receiver (atomic)
__device__ float  d_Smask[NMAX];                  // sum(mask) per receiver (atomic)
__device__ float  d_pool[HD];                     // atomic pooled sum of h
__device__ float  d_g[HD];                        // global supernode state
__device__ float  d_c[HD];                        // g@W_n_bot + b_n (per layer)

// ---------------- CSR build ----------------
__global__ void k_zero(int N) {
    int i = blockIdx.x * blockDim.x + threadIdx.x;
    if (i < N) {
        d_cursor[i] = 0;
        d_Smask[i] = 0.f;
        d_S4[i] = make_float4(0.f, 0.f, 0.f, 0.f);
    }
    if (i < HD) { d_g[i] = 0.f; d_pool[i] = 0.f; }
}

__global__ void k_count(const int* __restrict__ recv, int E) {
    int base = (blockIdx.x * blockDim.x + threadIdx.x) * 4;
    if (base + 4 <= E) {
        int4 r = *(const int4*)(recv + base);
        atomicAdd(&d_cursor[r.x], 1);
        atomicAdd(&d_cursor[r.y], 1);
        atomicAdd(&d_cursor[r.z], 1);
        atomicAdd(&d_cursor[r.w], 1);
    } else {
        for (int e = base; e < E; e++) atomicAdd(&d_cursor[recv[e]], 1);
    }
}

__global__ void k_scan(int N) {
    __shared__ int sh[1024];
    const int CH = 100;                 // 1024*100 >= 100000, beg 4-aligned
    int t = threadIdx.x;
    int beg = t * CH;
    int end = min(beg + CH, N);
    int s = 0;
    if (beg < N) {
        int i = beg;
        for (; i + 4 <= end; i += 4) {
            int4 v = *(const int4*)&d_cursor[i];
            s += v.x + v.y + v.z + v.w;
        }
        for (; i < end; i++) s += d_cursor[i];
    }
    sh[t] = s;
    __syncthreads();
    for (int off = 1; off < 1024; off <<= 1) {
        int v = (t >= off) ? sh[t - off] : 0;
        __syncthreads();
        sh[t] += v;
        __syncthreads();
    }
    int run = (t == 0) ? 0 : sh[t - 1];
    if (beg < N) {
        int i = beg;
        for (; i + 4 <= end; i += 4) {
            int4 v = *(const int4*)&d_cursor[i];
            int4 r;
            r.x = run; run += v.x;
            r.y = run; run += v.y;
            r.z = run; run += v.z;
            r.w = run; run += v.w;
            *(int4*)&d_rowptr[i] = r;
            *(int4*)&d_cursor[i] = r;
        }
        for (; i < end; i++) {
            int c = d_cursor[i];
            d_rowptr[i] = run; d_cursor[i] = run; run += c;
        }
    }
    if (t == 1023) d_rowptr[N] = sh[1023];
}

// fill CSR + accumulate layer-invariant edge-feature sums via distributed atomics
__device__ __forceinline__ void fill_one(int s, int r, float m, float4 f) {
    int pos = atomicAdd(&d_cursor[r], 1);
    d_csr[pos] = make_uint2((unsigned)s, __float_as_uint(m));
    atomicAdd(&d_S4[r].x, m * f.x);
    atomicAdd(&d_S4[r].y, m * f.y);
    atomicAdd(&d_S4[r].z, m * f.z);
    atomicAdd(&d_S4[r].w, m * f.w);
    atomicAdd(&d_Smask[r], m);
}

__global__ void k_fill(const int* __restrict__ send, const int* __restrict__ recv,
                       const float* __restrict__ mask, const float4* __restrict__ ef,
                       int E) {
    int base = (blockIdx.x * blockDim.x + threadIdx.x) * 2;
    if (base + 2 <= E) {
        int2 s = *(const int2*)(send + base);
        int2 r = *(const int2*)(recv + base);
        float2 m = *(const float2*)(mask + base);
        float4 f0 = ef[base], f1 = ef[base + 1];
        fill_one(s.x, r.x, m.x, f0);
        fill_one(s.y, r.y, m.y, f1);
    } else {
        for (int e = base; e < E; e++)
            fill_one(send[e], recv[e], mask[e], ef[e]);
    }
}

// ---------------- layer pipeline ----------------
// init: h0 = PQ@W_in + b_in ; V0=(1,0) ; T0 = [V0,h0] @ W_msg[0][0:34]
__global__ void k_init(const float2* __restrict__ PQ,
                       const float* __restrict__ W_in, const float* __restrict__ b_in,
                       const float* __restrict__ W_msg, int N) {
    __shared__ float sWin[2 * HD], sb[HD], sWt[34 * HD];
    for (int i = threadIdx.x; i < 2 * HD; i += blockDim.x) sWin[i] = W_in[i];
    for (int i = threadIdx.x; i < HD; i += blockDim.x) sb[i] = b_in[i];
    for (int i = threadIdx.x; i < 34 * HD; i += blockDim.x) sWt[i] = W_msg[i];
    __syncthreads();
    int warp = (blockIdx.x * blockDim.x + threadIdx.x) >> 5;
    int lane = threadIdx.x & 31;
    if (warp >= N) return;
    float2 pq = PQ[warp];
    float h = pq.x * sWin[lane] + pq.y * sWin[HD + lane] + sb[lane];
    if (lane == 0) d_V[warp] = make_float2(1.f, 0.f);
    float t = sWt[lane];  // V0=(1,0): 1*W_top[0][lane]
    #pragma unroll
    for (int k = 0; k < HD; k++)
        t += __shfl_sync(~0u, h, k) * sWt[(2 + k) * HD + lane];
    d_Th[warp * HD + lane] = __float2half_rn(t);
}

// aggregation: warp per receiver; fp16 T gathers; fused pool + u = h@Wn_top
__global__ void __launch_bounds__(256) k_agg(
        const float* __restrict__ W_msg, const float* __restrict__ b_msg,
        const float* __restrict__ W_n, int l, int N) {
    __shared__ float sWb[4 * HD], sb[HD], sWn[HD * HD];
    __shared__ float shp[8][HD];
    const float* Wl = W_msg + l * 38 * HD;
    const float* Wn = W_n + l * 64 * HD;
    for (int i = threadIdx.x; i < 4 * HD; i += blockDim.x) sWb[i] = Wl[34 * HD + i];
    for (int i = threadIdx.x; i < HD; i += blockDim.x) sb[i] = b_msg[l * HD + i];
    for (int i = threadIdx.x; i < HD * HD; i += blockDim.x) sWn[i] = Wn[i];
    __syncthreads();
    int warp = (blockIdx.x * blockDim.x + threadIdx.x) >> 5;
    int w = threadIdx.x >> 5;
    int lane = threadIdx.x & 31;
    float h = 0.f;
    if (warp < N) {
        float4 s4 = d_S4[warp];
        float sm = d_Smask[warp];
        float acc0 = s4.x * sWb[lane] + s4.y * sWb[HD + lane] +
                     s4.z * sWb[2 * HD + lane] + s4.w * sWb[3 * HD + lane] + sm * sb[lane];
        float acc1 = 0.f, acc2 = 0.f, acc3 = 0.f;
        int p = d_rowptr[warp], end = d_rowptr[warp + 1];
        if ((p & 1) && p < end) {  // align to uint4
            uint2 e = d_csr[p];
            acc1 += __uint_as_float(e.y) * __half2float(d_Th[e.x * HD + lane]);
            p++;
        }
        for (; p + 4 <= end; p += 4) {
            uint4 a = *(const uint4*)&d_csr[p];
            uint4 b = *(const uint4*)&d_csr[p + 2];
            acc0 += __uint_as_float(a.y) * __half2float(d_Th[a.x * HD + lane]);
            acc1 += __uint_as_float(a.w) * __half2float(d_Th[a.z * HD + lane]);
            acc2 += __uint_as_float(b.y) * __half2float(d_Th[b.x * HD + lane]);
            acc3 += __uint_as_float(b.w) * __half2float(d_Th[b.z * HD + lane]);
        }
        if (p + 2 <= end) {
            uint4 a = *(const uint4*)&d_csr[p];
            acc0 += __uint_as_float(a.y) * __half2float(d_Th[a.x * HD + lane]);
            acc1 += __uint_as_float(a.w) * __half2float(d_Th[a.z * HD + lane]);
            p += 2;
        }
        if (p < end) {
            uint2 e = d_csr[p];
            acc2 += __uint_as_float(e.y) * __half2float(d_Th[e.x * HD + lane]);
        }
        h = fmaxf(acc0 + acc1 + acc2 + acc3, 0.f);
    }
    shp[w][lane] = h;
    __syncthreads();
    if (w == 0) {
        float ps = 0.f;
        #pragma unroll
        for (int q = 0; q < 8; q++) ps += shp[q][lane];
        atomicAdd(&d_pool[lane], ps);
    }
    if (warp < N) {
        float u = 0.f;
        #pragma unroll
        for (int k = 0; k < HD; k++)
            u += __shfl_sync(~0u, h, k) * sWn[k * HD + lane];
        d_u[warp * HD + lane] = u;
    }
}

// global supernode update + precompute c = g_new @ W_n[32:64] + b_n ; re-zero pool
__global__ void k_g(const float* __restrict__ W_g, const float* __restrict__ b_g,
                    const float* __restrict__ W_n, const float* __restrict__ b_n,
                    int l, int N) {
    int j = threadIdx.x;  // 32 threads
    float p = d_pool[j] / (float)N;
    d_pool[j] = 0.f;
    float gold = d_g[j];
    const float* Wg = W_g + l * 64 * HD;
    float acc = b_g[l * HD + j];
    #pragma unroll
    for (int k = 0; k < HD; k++) {
        acc += __shfl_sync(~0u, gold, k) * Wg[k * HD + j];
        acc += __shfl_sync(~0u, p, k) * Wg[(HD + k) * HD + j];
    }
    float gn = fmaxf(acc, 0.f);
    d_g[j] = gn;
    const float* Wn = W_n + l * 64 * HD;
    float c = b_n[l * HD + j];
    #pragma unroll
    for (int k = 0; k < HD; k++)
        c += __shfl_sync(~0u, gn, k) * Wn[(HD + k) * HD + j];
    d_c[j] = c;
}

// node update: hn = relu(u + c); V += hn@W_out + b_out; T_next = [V,hn]@W_top(l+1)
__global__ void k_node(const float* __restrict__ W_out, const float* __restrict__ b_out,
                       const float* __restrict__ W_msg,
                       int l, int N, int last, float2* __restrict__ outV) {
    __shared__ float sWo[HD * 2], sWt[34 * HD], sc[HD];
    for (int i = threadIdx.x; i < HD * 2; i += blockDim.x) sWo[i] = W_out[l * HD * 2 + i];
    if (!last) {
        const float* Wt = W_msg + (l + 1) * 38 * HD;
        for (int i = threadIdx.x; i < 34 * HD; i += blockDim.x) sWt[i] = Wt[i];
    }
    for (int i = threadIdx.x; i < HD; i += blockDim.x) sc[i] = d_c[i];
    __syncthreads();
    int warp = (blockIdx.x * blockDim.x + threadIdx.x) >> 5;
    int lane = threadIdx.x & 31;
    if (warp >= N) return;
    float hn = fmaxf(d_u[warp * HD + lane] + sc[lane], 0.f);
    float v0 = hn * sWo[lane * 2 + 0];
    float v1 = hn * sWo[lane * 2 + 1];
    #pragma unroll
    for (int o = 16; o; o >>= 1) {
        v0 += __shfl_xor_sync(~0u, v0, o);
        v1 += __shfl_xor_sync(~0u, v1, o);
    }
    float2 v = d_V[warp];
    v.x += v0 + b_out[l * 2 + 0];
    v.y += v1 + b_out[l * 2 + 1];
    if (last) {
        if (lane == 0) outV[warp] = v;
    } else {
        if (lane == 0) d_V[warp] = v;
        float t = v.x * sWt[lane] + v.y * sWt[HD + lane];
        #pragma unroll
        for (int k = 0; k < HD; k++)
            t += __shfl_sync(~0u, hn, k) * sWt[(2 + k) * HD + lane];
        d_Th[warp * HD + lane] = __float2half_rn(t);
    }
}

// ---------------- launch ----------------
extern "C" void kernel_launch(void* const* d_in, const int* in_sizes, int n_in,
                              void* d_out, int out_size) {
    const float2* PQ    = (const float2*)d_in[0];
    const int*    send  = (const int*)d_in[1];
    const int*    recv  = (const int*)d_in[2];
    const float4* ef    = (const float4*)d_in[3];
    const float*  mask  = (const float*)d_in[4];
    const float*  W_in  = (const float*)d_in[5];
    const float*  b_in  = (const float*)d_in[6];
    const float*  W_msg = (const float*)d_in[7];
    const float*  b_msg = (const float*)d_in[8];
    const float*  W_g   = (const float*)d_in[9];
    const float*  b_g   = (const float*)d_in[10];
    const float*  W_n   = (const float*)d_in[11];
    const float*  b_n   = (const float*)d_in[12];
    const float*  W_out = (const float*)d_in[13];
    const float*  b_out = (const float*)d_in[14];

    int N = in_sizes[0] / 2;
    int E = in_sizes[1];
    int nwb = (N + 7) / 8;          // warp-per-node, 256-thread blocks
    int eb2 = (E + 511) / 512;      // 2 edges/thread
    int eb4 = (E + 1023) / 1024;    // 4 edges/thread

    k_zero<<<(N + 255) / 256, 256>>>(N);
    k_count<<<eb4, 256>>>(recv, E);
    k_scan<<<1, 1024>>>(N);
    k_fill<<<eb2, 256>>>(send, recv, mask, ef, E);
    k_init<<<nwb, 256>>>(PQ, W_in, b_in, W_msg, N);

    for (int l = 0; l < 3; l++) {
        k_agg<<<nwb, 256>>>(W_msg, b_msg, W_n, l, N);
        k_g<<<1, 32>>>(W_g, b_g, W_n, b_n, l, N);
        k_node<<<nwb, 256>>>(W_out, b_out, W_msg, l, N, l == 2, (float2*)d_out);
    }
}